// round 1
// baseline (speedup 1.0000x reference)
#include <cuda_runtime.h>
#include <cuda_bf16.h>
#include <math.h>

#define B_   1024
#define G_   2000
#define GS_  25
#define H1_  1024
#define H2_  512
#define C_   10
#define EPS_ 1e-5f

// ---------------- scratch (device globals; no allocation allowed) ----------
__device__ float d_g [B_ * G_];     // 8 MB
__device__ float d_h1[B_ * H1_];    // 4 MB
__device__ float d_h2[B_ * H2_];    // 2 MB
__device__ float d_scale1[H1_], d_shift1[H1_];
__device__ float d_scale2[H2_], d_shift2[H2_];

// ---------------- stage 1: grouped Linear(GS,1) + ReLU ---------------------
// g[b,j] = relu( sum_k x[b, j*25+k] * gene_w[j,k] + gene_b[j] )
#define GPB 128   // groups per block
__global__ void gene_kernel(const float* __restrict__ x,
                            const float* __restrict__ gw,
                            const float* __restrict__ gb,
                            float* __restrict__ g)
{
    __shared__ float sx[GPB * GS_];   // 12.8 KB
    const int b  = blockIdx.y;
    const int g0 = blockIdx.x * GPB;
    const int ng = min(GPB, G_ - g0);
    const float* xrow = x + (size_t)b * (G_ * GS_) + (size_t)g0 * GS_;
    const int total = ng * GS_;
    for (int i = threadIdx.x; i < total; i += blockDim.x)
        sx[i] = xrow[i];
    __syncthreads();
    const int j = threadIdx.x;
    if (j < ng) {
        const float* w = gw + (size_t)(g0 + j) * GS_;
        float acc = __ldg(gb + g0 + j);
#pragma unroll
        for (int k = 0; k < GS_; k++)
            acc = fmaf(sx[j * GS_ + k], __ldg(w + k), acc);
        g[(size_t)b * G_ + g0 + j] = fmaxf(acc, 0.0f);
    }
}

// ---------------- generic fp32 tiled GEMM: C = A[MxK] * B[KxN] + bias ------
// 64x64 block tile, BK=16, 256 threads, 4x4 micro-tile per thread.
// Requires M%64==0, N%64==0, K%16==0 (holds: 1024/1024/2000 and 1024/512/1024)
#define BM 64
#define BN 64
#define BK 16
__global__ __launch_bounds__(256, 2)
void gemm_bias(const float* __restrict__ A, const float* __restrict__ Bm,
               const float* __restrict__ bias, float* __restrict__ Cm,
               int M, int N, int K)
{
    __shared__ float As[BK][BM + 4];
    __shared__ float Bs[BK][BN];

    const int tid  = threadIdx.x;
    const int tx   = tid & 15;        // n direction
    const int ty   = tid >> 4;        // m direction
    const int row0 = blockIdx.y * BM;
    const int col0 = blockIdx.x * BN;

    const int arow  = tid >> 2;         // 0..63
    const int acol4 = (tid & 3) << 2;   // 0,4,8,12
    const int brow  = tid >> 4;         // 0..15
    const int bcol4 = (tid & 15) << 2;  // 0..60

    float acc[4][4] = {};

    for (int k0 = 0; k0 < K; k0 += BK) {
        float4 av = *(const float4*)(A + (size_t)(row0 + arow) * K + k0 + acol4);
        As[acol4 + 0][arow] = av.x;
        As[acol4 + 1][arow] = av.y;
        As[acol4 + 2][arow] = av.z;
        As[acol4 + 3][arow] = av.w;
        *(float4*)&Bs[brow][bcol4] =
            *(const float4*)(Bm + (size_t)(k0 + brow) * N + col0 + bcol4);
        __syncthreads();

#pragma unroll
        for (int k = 0; k < BK; k++) {
            float4 a  = *(const float4*)&As[k][ty << 2];
            float4 bv = *(const float4*)&Bs[k][tx << 2];
            float ar[4] = {a.x, a.y, a.z, a.w};
            float br[4] = {bv.x, bv.y, bv.z, bv.w};
#pragma unroll
            for (int i = 0; i < 4; i++)
#pragma unroll
                for (int j = 0; j < 4; j++)
                    acc[i][j] = fmaf(ar[i], br[j], acc[i][j]);
        }
        __syncthreads();
    }

#pragma unroll
    for (int i = 0; i < 4; i++) {
        const int r = row0 + (ty << 2) + i;
#pragma unroll
        for (int j = 0; j < 4; j++) {
            const int c = col0 + (tx << 2) + j;
            Cm[(size_t)r * N + c] = acc[i][j] + __ldg(bias + c);
        }
    }
}

// ---------------- BN stats: per-column mean/var -> scale/shift -------------
// block = (32,8); each block handles 32 columns.
__global__ void bn_stats(const float* __restrict__ h,
                         const float* __restrict__ gamma,
                         const float* __restrict__ beta,
                         float* __restrict__ scale,
                         float* __restrict__ shift, int N)
{
    const int c = blockIdx.x * 32 + threadIdx.x;
    const int r = threadIdx.y;
    float s = 0.f, s2 = 0.f;
    for (int i = r; i < B_; i += 8) {
        float v = h[(size_t)i * N + c];
        s += v; s2 += v * v;
    }
    __shared__ float ss[8][32], ss2[8][32];
    ss[r][threadIdx.x] = s;
    ss2[r][threadIdx.x] = s2;
    __syncthreads();
    if (r == 0) {
#pragma unroll
        for (int i = 1; i < 8; i++) { s += ss[i][threadIdx.x]; s2 += ss2[i][threadIdx.x]; }
        const float inv = 1.0f / (float)B_;
        float mu  = s * inv;
        float var = fmaxf(s2 * inv - mu * mu, 0.0f);
        float rs  = rsqrtf(var + EPS_);
        float sc  = __ldg(gamma + c) * rs;
        scale[c] = sc;
        shift[c] = __ldg(beta + c) - mu * sc;
    }
}

// ---------------- BN apply + ReLU in place ---------------------------------
__global__ void bn_apply(float* __restrict__ h,
                         const float* __restrict__ scale,
                         const float* __restrict__ shift, int N)
{
    const int col = blockIdx.x * blockDim.x + threadIdx.x;
    const int row = blockIdx.y;
    const size_t idx = (size_t)row * N + col;
    h[idx] = fmaxf(fmaf(h[idx], scale[col], shift[col]), 0.0f);
}

// ---------------- final: h2@Wout + g@Wres + biases -> softmax --------------
__global__ __launch_bounds__(256)
void final_kernel(const float* __restrict__ g, const float* __restrict__ h2,
                  const float* __restrict__ Wout, const float* __restrict__ bout,
                  const float* __restrict__ Wres, const float* __restrict__ bres,
                  float* __restrict__ out)
{
    const int b = blockIdx.x;
    float acc[C_] = {};

    for (int k = threadIdx.x; k < H2_; k += 256) {
        const float hv = h2[(size_t)b * H2_ + k];
        const float* w = Wout + (size_t)k * C_;
#pragma unroll
        for (int c = 0; c < C_; c++) acc[c] = fmaf(hv, __ldg(w + c), acc[c]);
    }
    for (int j = threadIdx.x; j < G_; j += 256) {
        const float gv = g[(size_t)b * G_ + j];
        const float* w = Wres + (size_t)j * C_;
#pragma unroll
        for (int c = 0; c < C_; c++) acc[c] = fmaf(gv, __ldg(w + c), acc[c]);
    }

    // warp reduce each channel
#pragma unroll
    for (int c = 0; c < C_; c++)
#pragma unroll
        for (int off = 16; off > 0; off >>= 1)
            acc[c] += __shfl_down_sync(0xFFFFFFFFu, acc[c], off);

    __shared__ float red[8][C_];
    const int warp = threadIdx.x >> 5;
    const int lane = threadIdx.x & 31;
    if (lane == 0)
#pragma unroll
        for (int c = 0; c < C_; c++) red[warp][c] = acc[c];
    __syncthreads();

    if (threadIdx.x == 0) {
        float logits[C_];
#pragma unroll
        for (int c = 0; c < C_; c++) {
            float v = __ldg(bout + c) + __ldg(bres + c);
#pragma unroll
            for (int w = 0; w < 8; w++) v += red[w][c];
            logits[c] = v;
        }
        float m = logits[0];
#pragma unroll
        for (int c = 1; c < C_; c++) m = fmaxf(m, logits[c]);
        float sum = 0.f;
#pragma unroll
        for (int c = 0; c < C_; c++) { logits[c] = __expf(logits[c] - m); sum += logits[c]; }
        const float inv = 1.0f / sum;
#pragma unroll
        for (int c = 0; c < C_; c++) out[(size_t)b * C_ + c] = logits[c] * inv;
    }
}

// ---------------- launch ----------------------------------------------------
extern "C" void kernel_launch(void* const* d_in, const int* in_sizes, int n_in,
                              void* d_out, int out_size)
{
    const float* x      = (const float*)d_in[0];
    const float* gene_w = (const float*)d_in[1];
    const float* gene_b = (const float*)d_in[2];
    const float* W1     = (const float*)d_in[3];
    const float* b1     = (const float*)d_in[4];
    const float* gamma1 = (const float*)d_in[5];
    const float* beta1  = (const float*)d_in[6];
    const float* W2     = (const float*)d_in[7];
    const float* b2     = (const float*)d_in[8];
    const float* gamma2 = (const float*)d_in[9];
    const float* beta2  = (const float*)d_in[10];
    const float* Wout   = (const float*)d_in[11];
    const float* bout   = (const float*)d_in[12];
    const float* Wres   = (const float*)d_in[13];
    const float* bres   = (const float*)d_in[14];
    float* out = (float*)d_out;

    float *g_p, *h1_p, *h2_p, *sc1_p, *sh1_p, *sc2_p, *sh2_p;
    cudaGetSymbolAddress((void**)&g_p,  d_g);
    cudaGetSymbolAddress((void**)&h1_p, d_h1);
    cudaGetSymbolAddress((void**)&h2_p, d_h2);
    cudaGetSymbolAddress((void**)&sc1_p, d_scale1);
    cudaGetSymbolAddress((void**)&sh1_p, d_shift1);
    cudaGetSymbolAddress((void**)&sc2_p, d_scale2);
    cudaGetSymbolAddress((void**)&sh2_p, d_shift2);

    // 1) grouped gene layer
    {
        dim3 grid((G_ + GPB - 1) / GPB, B_);
        gene_kernel<<<grid, GPB>>>(x, gene_w, gene_b, g_p);
    }
    // 2) h1_pre = g @ W1 + b1
    {
        dim3 grid(H1_ / BN, B_ / BM);
        gemm_bias<<<grid, 256>>>(g_p, W1, b1, h1_p, B_, H1_, G_);
    }
    // 3) BN1 stats + apply (ReLU fused)
    bn_stats<<<H1_ / 32, dim3(32, 8)>>>(h1_p, gamma1, beta1, sc1_p, sh1_p, H1_);
    bn_apply<<<dim3(H1_ / 256, B_), 256>>>(h1_p, sc1_p, sh1_p, H1_);
    // 4) h2_pre = h1 @ W2 + b2
    {
        dim3 grid(H2_ / BN, B_ / BM);
        gemm_bias<<<grid, 256>>>(h1_p, W2, b2, h2_p, B_, H2_, H1_);
    }
    // 5) BN2 stats + apply
    bn_stats<<<H2_ / 32, dim3(32, 8)>>>(h2_p, gamma2, beta2, sc2_p, sh2_p, H2_);
    bn_apply<<<dim3(H2_ / 256, B_), 256>>>(h2_p, sc2_p, sh2_p, H2_);
    // 6) fused output heads + softmax
    final_kernel<<<B_, 256>>>(g_p, h2_p, Wout, bout, Wres, bres, out);
}